// round 17
// baseline (speedup 1.0000x reference)
#include <cuda_runtime.h>
#include <cuda_fp16.h>
#include <cstdint>

// ---------------------------------------------------------------------------
// Problem dims (fixed by the dataset)
// ---------------------------------------------------------------------------
#define BATCH 8192
#define NDIM  4096
#define MDIM  4096
#define NGRP  (MDIM * 512)

// GEMM tiling (fp16 operands, fp32 accum)
#define CTA_M 128
#define CTA_N 128
#define BKH   64
#define KCHUNKS (NDIM / BKH)        // 64
#define STAGES 3
#define SROWH 72                    // padded row stride in halves (144 B)
#define STG_HALVES (128 * SROWH)    // 9216 halves = 18432 B per matrix per stage
#define STG_BYTES  (STG_HALVES * 2)
#define DYN_SMEM (2 * STAGES * STG_BYTES)   // 110592 B -> 2 CTAs/SM, 16 warps
// 8 warps: warp tile 32x64;  wm = (wid&3)*32, wn = (wid>>2)*64

// ---------------------------------------------------------------------------
// Scratch (16B-aligned: vector/cp.async access everywhere)
// ---------------------------------------------------------------------------
__device__ __align__(16) __half g_xrht[(size_t)BATCH * NDIM];  // 64 MB
__device__ __align__(16) __half g_W   [(size_t)MDIM  * NDIM];  // 32 MB
__device__ __align__(16) __half g_yrht[(size_t)BATCH * MDIM];  // 64 MB (fp16)

// ---------------------------------------------------------------------------
// Helpers
// ---------------------------------------------------------------------------
__device__ __forceinline__ uint32_t smem_u32(const void* p) {
    uint32_t a;
    asm("{ .reg .u64 t; cvta.to.shared.u64 t, %1; cvt.u32.u64 %0, t; }" : "=r"(a) : "l"(p));
    return a;
}
__device__ __forceinline__ void cp_async16(uint32_t dst, const void* src) {
    asm volatile("cp.async.cg.shared.global [%0], [%1], 16;" :: "r"(dst), "l"(src));
}
__device__ __forceinline__ void cp_commit() {
    asm volatile("cp.async.commit_group;" ::: "memory");
}
template <int N>
__device__ __forceinline__ void cp_wait() {
    asm volatile("cp.async.wait_group %0;" :: "n"(N) : "memory");
}
__device__ __forceinline__ void mma_f16(float* d, const uint32_t* a, const uint32_t* b) {
    asm volatile(
        "mma.sync.aligned.m16n8k16.row.col.f32.f16.f16.f32 "
        "{%0,%1,%2,%3}, {%4,%5,%6,%7}, {%8,%9}, {%0,%1,%2,%3};"
        : "+f"(d[0]), "+f"(d[1]), "+f"(d[2]), "+f"(d[3])
        : "r"(a[0]), "r"(a[1]), "r"(a[2]), "r"(a[3]), "r"(b[0]), "r"(b[1]));
}
__device__ __forceinline__ void bfly4(float& e0, float& e1, float& e2, float& e3) {
    float u0 = e0 + e1, u1 = e0 - e1, u2 = e2 + e3, u3 = e2 - e3;
    e0 = u0 + u2; e1 = u1 + u3; e2 = u0 - u2; e3 = u1 - u3;
}
// In-register H_16 (4 butterfly stages) on e[0..15]
__device__ __forceinline__ void h16(float* e) {
    bfly4(e[0], e[1], e[2], e[3]);   bfly4(e[4], e[5], e[6], e[7]);
    bfly4(e[8], e[9], e[10], e[11]); bfly4(e[12], e[13], e[14], e[15]);
    bfly4(e[0], e[4], e[8], e[12]);  bfly4(e[1], e[5], e[9], e[13]);
    bfly4(e[2], e[6], e[10], e[14]); bfly4(e[3], e[7], e[11], e[15]);
}

// FHT smem: layout A = i + (i>>4); layout B = i + (i>>8)*16. Max idx 4350.
#define FHT_SMEM 4352

// ---------------------------------------------------------------------------
// Kernel 1: x_rht = fp16(FHT(x*SV)/64) — 3 passes, 16 elems/thread in regs
// ---------------------------------------------------------------------------
__global__ __launch_bounds__(256) void fht_pre_kernel(
    const float* __restrict__ x, const float* __restrict__ SV)
{
    __shared__ float s[FHT_SMEM];
    const int row = blockIdx.x;
    const int t = threadIdx.x;
    float e[16];

    // Pass 1: stages h=1..8 on contiguous 16
    {
        const float* xr = x + (size_t)row * NDIM + t * 16;
        const float* sv = SV + t * 16;
#pragma unroll
        for (int q = 0; q < 4; q++) {
            float4 v = *(const float4*)(xr + 4 * q);
            float4 w = *(const float4*)(sv + 4 * q);
            e[4 * q + 0] = v.x * w.x; e[4 * q + 1] = v.y * w.y;
            e[4 * q + 2] = v.z * w.z; e[4 * q + 3] = v.w * w.w;
        }
        h16(e);
#pragma unroll
        for (int o = 0; o < 16; o++) s[17 * t + o] = e[o];   // layout A
    }
    __syncthreads();

    // Pass 2: stages h=16..128; i = b*256 + j*16 + r
    {
        const int r = t & 15, b = t >> 4;
        const int baseA = b * 272 + r;
#pragma unroll
        for (int j = 0; j < 16; j++) e[j] = s[baseA + j * 17];
        h16(e);
        __syncthreads();
        const int baseB = b * 272 + r;                       // layout B
#pragma unroll
        for (int j = 0; j < 16; j++) s[baseB + j * 16] = e[j];
    }
    __syncthreads();

    // Pass 3: stages h=256..2048; i = j*256 + t
    {
#pragma unroll
        for (int j = 0; j < 16; j++) e[j] = s[j * 272 + t];
        h16(e);
        const float sc = 0.015625f;
        __half* o = g_xrht + (size_t)row * NDIM;
#pragma unroll
        for (int j = 0; j < 16; j++) o[j * 256 + t] = __float2half_rn(e[j] * sc);
    }
}

// ---------------------------------------------------------------------------
// Kernel 2: dequantize W -> fp16
// ---------------------------------------------------------------------------
__global__ __launch_bounds__(256) void dequant_kernel(
    const int* __restrict__ Qidxs, const int* __restrict__ Qidxs2,
    const float* __restrict__ cb, const float* __restrict__ cb2,
    const float* __restrict__ irs_p)
{
    int g = blockIdx.x * blockDim.x + threadIdx.x;
    if (g >= NGRP) return;
    const float irs = __ldg(irs_p);
    const int q  = Qidxs[g];
    const int q2 = Qidxs2[g];

    float4 c0 = __ldg((const float4*)cb  + q  * 2);
    float4 c1 = __ldg((const float4*)cb  + q  * 2 + 1);
    float4 d0 = __ldg((const float4*)cb2 + q2 * 2);
    float4 d1 = __ldg((const float4*)cb2 + q2 * 2 + 1);

    __half2 h0 = __floats2half2_rn(fmaf(irs, d0.x, c0.x), fmaf(irs, d0.y, c0.y));
    __half2 h1 = __floats2half2_rn(fmaf(irs, d0.z, c0.z), fmaf(irs, d0.w, c0.w));
    __half2 h2 = __floats2half2_rn(fmaf(irs, d1.x, c1.x), fmaf(irs, d1.y, c1.y));
    __half2 h3 = __floats2half2_rn(fmaf(irs, d1.z, c1.z), fmaf(irs, d1.w, c1.w));

    uint4 u;
    u.x = *reinterpret_cast<uint32_t*>(&h0);
    u.y = *reinterpret_cast<uint32_t*>(&h1);
    u.z = *reinterpret_cast<uint32_t*>(&h2);
    u.w = *reinterpret_cast<uint32_t*>(&h3);
    *(uint4*)(g_W + (size_t)g * 8) = u;
}

// ---------------------------------------------------------------------------
// Kernel 3: fp16 mma.sync GEMM — 8 warps (32x64 warp tiles), 3-stage,
// 2 CTAs/SM (16 warps/SM = 4/SMSP), clean 6.92-wave tail.
// ---------------------------------------------------------------------------
__global__ __launch_bounds__(256, 2) void gemm_f16_kernel()
{
    extern __shared__ __half smh[];

    const int tid  = threadIdx.x;
    const int wid  = tid >> 5;
    const int lane = tid & 31;
    const int gid  = lane >> 2;
    const int tig  = lane & 3;
    const int wm   = (wid & 3) * 32;     // 4 warps along M
    const int wn   = (wid >> 2) * 64;    // 2 warps along N

    const int brow = blockIdx.y * CTA_M;
    const int bcol = blockIdx.x * CTA_N;

    const uint32_t sbase = smem_u32(smh);

    float acc[2][8][4];
#pragma unroll
    for (int i = 0; i < 2; i++)
#pragma unroll
        for (int j = 0; j < 8; j++)
#pragma unroll
            for (int q = 0; q < 4; q++) acc[i][j][q] = 0.0f;

    // loader: 1024 cp.asyncs per matrix per stage / 256 threads = 4 each
    auto load_stage = [&](int st, int kc) {
        const int k0 = kc * BKH;
        const uint32_t bA = sbase + (uint32_t)st * STG_BYTES;
        const uint32_t bB = sbase + (uint32_t)(STAGES + st) * STG_BYTES;
#pragma unroll
        for (int s = 0; s < 4; s++) {
            int c = s * 256 + tid;
            int row = c >> 3, seg = c & 7;
            cp_async16(bA + row * (SROWH * 2) + seg * 16,
                       g_xrht + (size_t)(brow + row) * NDIM + k0 + seg * 8);
            cp_async16(bB + row * (SROWH * 2) + seg * 16,
                       g_W    + (size_t)(bcol + row) * NDIM + k0 + seg * 8);
        }
    };

#pragma unroll
    for (int s = 0; s < STAGES - 1; s++) {
        load_stage(s, s);
        cp_commit();
    }

    for (int kc = 0; kc < KCHUNKS; kc++) {
        cp_wait<STAGES - 2>();
        __syncthreads();

        if (kc + STAGES - 1 < KCHUNKS)
            load_stage((kc + STAGES - 1) % STAGES, kc + STAGES - 1);
        cp_commit();

        const int st = kc % STAGES;
        const __half* Ast = smh + (size_t)st * STG_HALVES;
        const __half* Bst = smh + (size_t)(STAGES + st) * STG_HALVES;

#pragma unroll
        for (int ks = 0; ks < 4; ks++) {
            const int k = ks * 16;
            uint32_t af[2][4], bf[8][2];
#pragma unroll
            for (int i = 0; i < 2; i++) {
                const __half* ap = Ast + (wm + i * 16 + gid) * SROWH + k + tig * 2;
                af[i][0] = *(const uint32_t*)(ap);
                af[i][1] = *(const uint32_t*)(ap + 8 * SROWH);
                af[i][2] = *(const uint32_t*)(ap + 8);
                af[i][3] = *(const uint32_t*)(ap + 8 * SROWH + 8);
            }
#pragma unroll
            for (int j = 0; j < 8; j++) {
                const __half* bp = Bst + (wn + j * 8 + gid) * SROWH + k + tig * 2;
                bf[j][0] = *(const uint32_t*)(bp);
                bf[j][1] = *(const uint32_t*)(bp + 8);
            }
#pragma unroll
            for (int i = 0; i < 2; i++)
#pragma unroll
                for (int j = 0; j < 8; j++)
                    mma_f16(acc[i][j], af[i], bf[j]);
        }
    }

    // epilogue: fp16 y_rht (c0 even -> 4B-aligned half2 stores)
#pragma unroll
    for (int i = 0; i < 2; i++) {
        const int r0 = brow + wm + i * 16 + gid;
#pragma unroll
        for (int j = 0; j < 8; j++) {
            const int c0 = bcol + wn + j * 8 + tig * 2;
            __half2 lo = __floats2half2_rn(acc[i][j][0], acc[i][j][1]);
            __half2 hi = __floats2half2_rn(acc[i][j][2], acc[i][j][3]);
            *(__half2*)&g_yrht[(size_t)r0 * MDIM + c0] = lo;
            *(__half2*)&g_yrht[(size_t)(r0 + 8) * MDIM + c0] = hi;
        }
    }
}

// ---------------------------------------------------------------------------
// Kernel 4: y = FHT(y_rht) * SU * Wscale / 64 — 3-pass register FHT
// ---------------------------------------------------------------------------
__global__ __launch_bounds__(256) void fht_post_kernel(
    float* __restrict__ out, const float* __restrict__ SU,
    const float* __restrict__ wscale_p)
{
    __shared__ float s[FHT_SMEM];
    const int row = blockIdx.x;
    const int t = threadIdx.x;
    float e[16];

    {
        // 16 halves = 32 bytes = TWO uint4 loads
        const __half* yr = g_yrht + (size_t)row * MDIM + t * 16;
        uint4 u0 = *(const uint4*)(yr);
        uint4 u1 = *(const uint4*)(yr + 8);
        const __half2* hp0 = (const __half2*)&u0;
        const __half2* hp1 = (const __half2*)&u1;
#pragma unroll
        for (int q = 0; q < 4; q++) {
            float2 f0 = __half22float2(hp0[q]);
            float2 f1 = __half22float2(hp1[q]);
            e[2 * q]     = f0.x; e[2 * q + 1]     = f0.y;
            e[8 + 2 * q] = f1.x; e[8 + 2 * q + 1] = f1.y;
        }
        h16(e);
#pragma unroll
        for (int o = 0; o < 16; o++) s[17 * t + o] = e[o];
    }
    __syncthreads();

    {
        const int r = t & 15, b = t >> 4;
        const int baseA = b * 272 + r;
#pragma unroll
        for (int j = 0; j < 16; j++) e[j] = s[baseA + j * 17];
        h16(e);
        __syncthreads();
        const int baseB = b * 272 + r;
#pragma unroll
        for (int j = 0; j < 16; j++) s[baseB + j * 16] = e[j];
    }
    __syncthreads();

    {
#pragma unroll
        for (int j = 0; j < 16; j++) e[j] = s[j * 272 + t];
        h16(e);
        const float ws = __ldg(wscale_p) * 0.015625f;
        float* o = out + (size_t)row * MDIM;
#pragma unroll
        for (int j = 0; j < 16; j++)
            o[j * 256 + t] = e[j] * SU[j * 256 + t] * ws;
    }
}

// ---------------------------------------------------------------------------
// Launch
// ---------------------------------------------------------------------------
extern "C" void kernel_launch(void* const* d_in, const int* in_sizes, int n_in,
                              void* d_out, int out_size)
{
    const float* x      = (const float*)d_in[0];
    const int*   Qidxs  = (const int*)  d_in[1];
    const int*   Qidxs2 = (const int*)  d_in[2];
    const float* SU     = (const float*)d_in[3];
    const float* SV     = (const float*)d_in[4];
    const float* cb     = (const float*)d_in[5];
    const float* cb2    = (const float*)d_in[6];
    const float* Wscale = (const float*)d_in[7];
    const float* irs    = (const float*)d_in[8];
    float* out = (float*)d_out;
    (void)in_sizes; (void)n_in; (void)out_size;

    cudaFuncSetAttribute(gemm_f16_kernel,
                         cudaFuncAttributeMaxDynamicSharedMemorySize, DYN_SMEM);

    fht_pre_kernel<<<BATCH, 256>>>(x, SV);
    dequant_kernel<<<NGRP / 256, 256>>>(Qidxs, Qidxs2, cb, cb2, irs);

    dim3 grid(MDIM / CTA_N, BATCH / CTA_M);
    gemm_f16_kernel<<<grid, 256, DYN_SMEM>>>();

    fht_post_kernel<<<BATCH, 256>>>(out, SU, Wscale);
}